// round 15
// baseline (speedup 1.0000x reference)
#include <cuda_runtime.h>
#include <cuda_fp16.h>
#include <cstdint>

#define D_IN   128
#define HID    512
#define D_OUTK 128
#define NOBJ   100000
#define NT     200000

#define BM 128
#define BN 128
#define BK 64
#define KTILE_H 8192                     // halfs per 16KB tile (128 rows x 64 halfs)
#define KTILE_B 16384
#define STAGE_BYTES (2 * KTILE_B)        // A + B = 32 KB
#define NSTAGE 3
#define SMEMB (1024 + NSTAGE * STAGE_BYTES)
#define NPANEL_T 1563                    // ceil(NT/128)
#define NPANEL_O 782                     // ceil(NOBJ/128)

// Scratch (device globals — no allocation allowed). Zero-init; tails beyond M
// are never written and stay zero across replays.
__device__ __align__(16) __half g_h[(size_t)NPANEL_T * 8 * KTILE_H];   // packed tiles
__device__ __align__(16) float  g_pooled[(size_t)NOBJ * HID];
__device__ __align__(16) __half g_ph[(size_t)NPANEL_O * 8 * KTILE_H];  // pooledh packed
__device__ __align__(16) __half g_tp[(size_t)NPANEL_O * 8 * KTILE_H];  // tmph packed
__device__ __align__(16) float  g_counts[NOBJ];
__device__ __align__(16) __half g_objth[(size_t)NOBJ * D_IN];
__device__ __align__(16) __half g_predth[(size_t)NT * D_IN];
// Weights packed as [nblock][ktile][16KB swizzled tile]
__device__ __align__(16) __half g_W1P[(size_t)4 * 6 * KTILE_H];
__device__ __align__(16) __half g_W2P[(size_t)9 * 8 * KTILE_H];
__device__ __align__(16) __half g_W3P[(size_t)4 * 8 * KTILE_H];
__device__ __align__(16) __half g_W4P[(size_t)1 * 8 * KTILE_H];

// ---------------------------------------------------------------------------
__device__ __forceinline__ void mma_f16(float* c, const uint32_t* a, const uint32_t* b) {
    asm volatile(
        "mma.sync.aligned.m16n8k16.row.col.f32.f16.f16.f32 "
        "{%0,%1,%2,%3}, {%4,%5,%6,%7}, {%8,%9}, {%0,%1,%2,%3};"
        : "+f"(c[0]), "+f"(c[1]), "+f"(c[2]), "+f"(c[3])
        : "r"(a[0]), "r"(a[1]), "r"(a[2]), "r"(a[3]), "r"(b[0]), "r"(b[1]));
}

__device__ __forceinline__ void ldsm4(uint32_t& r0, uint32_t& r1, uint32_t& r2,
                                      uint32_t& r3, uint32_t addr) {
    asm volatile("ldmatrix.sync.aligned.m8n8.x4.shared.b16 {%0,%1,%2,%3}, [%4];"
                 : "=r"(r0), "=r"(r1), "=r"(r2), "=r"(r3) : "r"(addr));
}

__device__ __forceinline__ void cp16(uint32_t d, const void* s, int sz) {
    asm volatile("cp.async.cg.shared.global [%0], [%1], 16, %2;"
                 :: "r"(d), "l"(s), "r"(sz));
}
#define CP_COMMIT() asm volatile("cp.async.commit_group;" ::: "memory")
#define CP_WAIT1()  asm volatile("cp.async.wait_group 1;" ::: "memory")

__device__ __forceinline__ void bulk_g2s(uint32_t dst, const void* src,
                                         int bytes, uint32_t mbar) {
    asm volatile("cp.async.bulk.shared::cta.global.mbarrier::complete_tx::bytes "
                 "[%0], [%1], %2, [%3];"
                 :: "r"(dst), "l"(src), "r"(bytes), "r"(mbar) : "memory");
}

#define MBARRIER_INIT(mbar, count) \
    asm volatile("mbarrier.init.shared.b64 [%0], %1;" \
                 :: "r"((uint32_t)(mbar)), "r"((uint32_t)(count)) : "memory")
#define MBARRIER_EXPECT_TX(mbar, tx) \
    asm volatile("mbarrier.arrive.expect_tx.shared.b64 _, [%0], %1;" \
                 :: "r"((uint32_t)(mbar)), "r"((uint32_t)(tx)) : "memory")
#define MBARRIER_ARRIVE(mbar) \
    asm volatile("mbarrier.arrive.shared.b64 _, [%0];" \
                 :: "r"((uint32_t)(mbar)) : "memory")
#define MBARRIER_WAIT_PARITY(mbar_smem_addr, phase_parity) do { \
    uint32_t _mbar = (uint32_t)(mbar_smem_addr); \
    uint32_t _parity = (uint32_t)(phase_parity); \
    uint32_t _done; \
    asm volatile("{\n\t.reg .pred p;\n\t" \
        "mbarrier.try_wait.parity.acquire.cta.shared::cta.b64 p, [%1], %2;\n\t" \
        "selp.b32 %0, 1, 0, p;\n\t}" \
        : "=r"(_done) : "r"(_mbar), "r"(_parity) : "memory"); \
    if (!_done) { \
        asm volatile("{\n\t.reg .pred P1;\n\t" \
            "WAIT_LOOP_%=:\n\t" \
            "mbarrier.try_wait.parity.acquire.cta.shared::cta.b64 P1, [%0], %1, 0x989680;\n\t" \
            "@P1 bra.uni WAIT_DONE_%=;\n\t" \
            "bra.uni WAIT_LOOP_%=;\n\t" \
            "WAIT_DONE_%=:\n\t}" \
            :: "r"(_mbar), "r"(_parity) : "memory"); \
    } \
} while(0)

__device__ __forceinline__ void red_add_v4(float* addr, float a, float b,
                                           float c, float d) {
    asm volatile("red.global.add.v4.f32 [%0], {%1, %2, %3, %4};"
                 :: "l"(addr), "f"(a), "f"(b), "f"(c), "f"(d) : "memory");
}

// Packed tile offset (in halfs) for element (row r, col c) of a K=512 matrix.
__device__ __forceinline__ size_t packed_off(int r, int c) {
    int p = r >> 7, m = r & 127, kt = c >> 6, ch = (c & 63) >> 3, rem = c & 7;
    return ((size_t)(p * 8 + kt)) * KTILE_H
         + (size_t)((m * 128 + ((ch ^ (m & 7)) * 16)) >> 1) + rem;
}

// ---------------------------------------------------------------------------
__global__ void zero_counts() {
    int i = blockIdx.x * blockDim.x + threadIdx.x;
    if (i < NOBJ) g_counts[i] = 0.f;
}

#define NB_POOL  50000
#define NB_OBJ   12500
#define NB_PRED  25000
#define NB_W1    768
#define NB_W2    2304
#define NB_W3    1024
#define NB_W4    256
#define NB_CNT   782
#define NB_TOTAL (NB_POOL + NB_OBJ + NB_PRED + NB_W1 + NB_W2 + NB_W3 + NB_W4 + NB_CNT)

__device__ __forceinline__ void cvt_sec(const float* src, __half* dst, int i) {
    float4 v = ((const float4*)src)[i];
    __half2* d2 = (__half2*)dst;
    d2[2 * i]     = __floats2half2_rn(v.x, v.y);
    d2[2 * i + 1] = __floats2half2_rn(v.z, v.w);
}
// Pack W (K x N, row-major) into swizzled tiles WP[nb][kt][16KB]
__device__ __forceinline__ void cvtT_pack(const float* W, __half* WP, int K, int N, int idx) {
    int n = idx / K, k = idx - n * K;
    int nb = n >> 7, nl = n & 127, kt = k >> 6, ch = (k & 63) >> 3, rem = k & 7;
    int KTI = K / 64;
    size_t off = ((size_t)(nb * KTI + kt)) * KTILE_H
               + (size_t)((nl * 128 + ((ch ^ (nl & 7)) * 16)) >> 1) + rem;
    WP[off] = __float2half_rn(W[(size_t)k * N + n]);
}

__global__ void prep_kernel(const float* __restrict__ obj, const float* __restrict__ pred,
                            const int* __restrict__ edges,
                            const float* __restrict__ W1, const float* __restrict__ W2,
                            const float* __restrict__ W3, const float* __restrict__ W4)
{
    int b = blockIdx.x;
    int t = threadIdx.x;
    if (b < NB_POOL) {
        int i = b * 256 + t;
        ((float4*)g_pooled)[i] = make_float4(0.f, 0.f, 0.f, 0.f);
        return;
    }
    b -= NB_POOL;
    if (b < NB_OBJ)  { cvt_sec(obj,  g_objth,  b * 256 + t); return; }
    b -= NB_OBJ;
    if (b < NB_PRED) { cvt_sec(pred, g_predth, b * 256 + t); return; }
    b -= NB_PRED;
    if (b < NB_W1) { cvtT_pack(W1, g_W1P, 384, 512,  b * 256 + t); return; }
    b -= NB_W1;
    if (b < NB_W2) { cvtT_pack(W2, g_W2P, 512, 1152, b * 256 + t); return; }
    b -= NB_W2;
    if (b < NB_W3) { cvtT_pack(W3, g_W3P, 512, 512,  b * 256 + t); return; }
    b -= NB_W3;
    if (b < NB_W4) { cvtT_pack(W4, g_W4P, 512, 128,  b * 256 + t); return; }
    b -= NB_W4;
    {
        int e = b * 256 + t;
        if (e < NT) {
            atomicAdd(&g_counts[edges[2 * e]],     1.f);
            atomicAdd(&g_counts[edges[2 * e + 1]], 1.f);
        }
    }
}

// g_ph[packed(r,c)] = half(pooled[r][c] / max(counts[r],1))
__global__ void normalize_h() {
    int i = blockIdx.x * blockDim.x + threadIdx.x;
    if (i < (NOBJ * HID) / 4) {
        int r = i >> 7;
        int c = (i & 127) * 4;
        float sc = 1.f / fmaxf(g_counts[r], 1.f);
        float4 v = ((const float4*)g_pooled)[i];
        __half* dst = g_ph + packed_off(r, c);
        *(__half2*)(dst)     = __floats2half2_rn(v.x * sc, v.y * sc);
        *(__half2*)(dst + 2) = __floats2half2_rn(v.z * sc, v.w * sc);
    }
}

// ---------------------------------------------------------------------------
// MF = m-fragments per warp (2 -> 32x64 tile, 256 thr; 4 -> 64x64 tile, 128 thr).
// KIND 0: g_h(packed) = h(relu(gather @ W1 + b1))     M=NT,   K=384  [cp.async, per-block]
// KIND 1: scatter/out_p from relu(h @ W2 + b2)        M=NT,   K=512  [bulk, persistent]
// KIND 2: g_tp(packed) = h(relu(ph @ W3 + b3))        M=NOBJ, K=512  [bulk, persistent]
// KIND 3: out_obj = relu(tp @ W4 + b4)                M=NOBJ, K=512  [bulk, persistent]
template<int KIND, int MF>
__global__ void __launch_bounds__(512 / MF, 2) hgemm(const int* __restrict__ edges,
                                                     const float* __restrict__ bias,
                                                     float* __restrict__ out, int M)
{
    constexpr int K  = (KIND == 0) ? 384 : 512;
    constexpr int KT = K / BK;
    constexpr int MWARPS = 8 / MF;
    constexpr int NTH = MWARPS * 2 * 32;
    constexpr int NWARPS = NTH / 32;
    constexpr int LIT = 1024 / NTH;

    extern __shared__ __align__(16) char sh[];
    uint32_t sm = (uint32_t)__cvta_generic_to_shared(sh);
    uint32_t tiles = sm + 1024;
    // mbarriers: full[b] at sm + b*8, empty[b] at sm + 64 + b*8

    int tid = threadIdx.x, lane = tid & 31, w = tid >> 5;
    int wm = w % MWARPS, wn = w / MWARPS;
    int gr = lane >> 2, ct = lane & 3;
    int sel = lane >> 3, lr = lane & 7;
    int col0 = blockIdx.x * BN;

    int mode = 0, pcol = 0;
    if (KIND == 1) {
        int bx = blockIdx.x;
        if (bx < 4)       { mode = 0; pcol = bx * 128; }
        else if (bx == 4) { mode = 1; pcol = 0; }
        else              { mode = 2; pcol = (bx - 5) * 128; }
    }

    const __half* Bsrc = (KIND == 0) ? g_W1P + (size_t)(blockIdx.x * 6) * KTILE_H
                       : (KIND == 1) ? g_W2P + (size_t)(blockIdx.x * 8) * KTILE_H
                       : (KIND == 2) ? g_W3P + (size_t)(blockIdx.x * 8) * KTILE_H
                                     : g_W4P;
    const __half* Abase = (KIND == 1) ? g_h : (KIND == 2) ? g_ph : g_tp;

    float acc[MF][8][4];
    int a_row[MF];
#pragma unroll
    for (int mf = 0; mf < MF; mf++)
        a_row[mf] = wm * (16 * MF) + mf * 16 + lr + ((sel & 1) << 3);
    int b_row[4];
#pragma unroll
    for (int p = 0; p < 4; p++)
        b_row[p] = wn * 64 + p * 16 + lr + ((sel >> 1) << 3);

    auto acc_clear = [&]() {
#pragma unroll
        for (int i = 0; i < MF; i++)
#pragma unroll
            for (int j = 0; j < 8; j++)
#pragma unroll
                for (int k = 0; k < 4; k++) acc[i][j][k] = 0.f;
    };

    auto mma_stage = [&](int b) {
        uint32_t abase = tiles + (uint32_t)b * STAGE_BYTES;
        uint32_t bbase = abase + KTILE_B;
#pragma unroll
        for (int kb = 0; kb < BK / 16; kb++) {
            uint32_t a[MF][4], bf[8][2];
            int a_ch = 2 * kb + (sel >> 1);
#pragma unroll
            for (int mf = 0; mf < MF; mf++) {
                int r = a_row[mf];
                ldsm4(a[mf][0], a[mf][1], a[mf][2], a[mf][3],
                      abase + (uint32_t)(r * 128 + ((a_ch ^ (r & 7)) * 16)));
            }
            int b_ch = 2 * kb + (sel & 1);
#pragma unroll
            for (int p = 0; p < 4; p++) {
                int r = b_row[p];
                ldsm4(bf[2 * p][0], bf[2 * p][1], bf[2 * p + 1][0], bf[2 * p + 1][1],
                      bbase + (uint32_t)(r * 128 + ((b_ch ^ (r & 7)) * 16)));
            }
#pragma unroll
            for (int mf = 0; mf < MF; mf++)
#pragma unroll
                for (int nf = 0; nf < 8; nf++)
                    mma_f16(acc[mf][nf], a[mf], bf[nf]);
        }
    };

    float bb[8][2];
#pragma unroll
    for (int nf = 0; nf < 8; nf++) {
        int c = col0 + wn * 64 + nf * 8 + ct * 2;
        bb[nf][0] = bias[c]; bb[nf][1] = bias[c + 1];
    }

    auto epilogue = [&](int row0) {
        if (KIND == 1 && mode != 1) {
            int halfsel = ct & 1;
            int q = ct >> 1;
#pragma unroll
            for (int mf = 0; mf < MF; mf++) {
                int rbase = row0 + wm * (16 * MF) + mf * 16 + gr;
                int myrow = rbase + (halfsel ? 8 : 0);
                bool valid = myrow < M;
                int sidx = 0;
                if (valid) sidx = (mode == 0) ? edges[2 * myrow] : edges[2 * myrow + 1];
                float* dstrow = g_pooled + (size_t)sidx * HID + pcol + wn * 64 + q * 4;
#pragma unroll
                for (int nf = 0; nf < 8; nf++) {
                    float v0 = fmaxf(acc[mf][nf][0] + bb[nf][0], 0.f);
                    float v1 = fmaxf(acc[mf][nf][1] + bb[nf][1], 0.f);
                    float v2 = fmaxf(acc[mf][nf][2] + bb[nf][0], 0.f);
                    float v3 = fmaxf(acc[mf][nf][3] + bb[nf][1], 0.f);
                    float s0 = halfsel ? v0 : v2;
                    float s1 = halfsel ? v1 : v3;
                    float p0 = __shfl_xor_sync(0xffffffffu, s0, 1);
                    float p1 = __shfl_xor_sync(0xffffffffu, s1, 1);
                    float o0 = halfsel ? p0 : v0;
                    float o1 = halfsel ? p1 : v1;
                    float o2 = halfsel ? v2 : p0;
                    float o3 = halfsel ? v3 : p1;
                    if (valid) red_add_v4(dstrow + nf * 8, o0, o1, o2, o3);
                }
            }
        } else {
#pragma unroll
            for (int mf = 0; mf < MF; mf++)
#pragma unroll
                for (int half = 0; half < 2; half++) {
                    int r = row0 + wm * (16 * MF) + mf * 16 + gr + half * 8;
                    if (r >= M) continue;
                    if (KIND == 0 || KIND == 2) {
                        __half* base = (KIND == 0) ? g_h : g_tp;
#pragma unroll
                        for (int nf = 0; nf < 8; nf++) {
                            int c = col0 + wn * 64 + nf * 8 + ct * 2;
                            float x = fmaxf(acc[mf][nf][half * 2 + 0] + bb[nf][0], 0.f);
                            float y = fmaxf(acc[mf][nf][half * 2 + 1] + bb[nf][1], 0.f);
                            *(__half2*)(base + packed_off(r, c)) = __floats2half2_rn(x, y);
                        }
                    } else {  // KIND 3 or KIND 1 mode==1
                        int cbase = wn * 64 + ct * 2;
                        float* dst = out + (size_t)r * D_OUTK + cbase;
#pragma unroll
                        for (int nf = 0; nf < 8; nf++) {
                            float2 o;
                            o.x = fmaxf(acc[mf][nf][half * 2 + 0] + bb[nf][0], 0.f);
                            o.y = fmaxf(acc[mf][nf][half * 2 + 1] + bb[nf][1], 0.f);
                            *(float2*)(dst + nf * 8) = o;
                        }
                    }
                }
        }
    };

    if (KIND == 0) {
        // ---- cp.async path (gather A + contiguous packed B), one block per tile ----
        int row0 = blockIdx.y * BM;
        acc_clear();
        auto load_stage = [&](int kt) {
            int k0 = kt * BK;
            uint32_t ab = tiles + (uint32_t)(kt % NSTAGE) * STAGE_BYTES;
            uint32_t bbuf = ab + KTILE_B;
#pragma unroll
            for (int i = 0; i < LIT; i++) {
                int f = tid + i * NTH;
                int m = f >> 3, ch = f & 7;
                int mg = row0 + m;
                int sz = (mg < M) ? 16 : 0;
                int mc = (mg < M) ? mg : M - 1;
                int region = k0 >> 7;
                int bo = (k0 & 127) * 2;
                const char* src;
                if (region == 0)      src = (const char*)(g_objth  + (size_t)edges[2 * mc]     * 128) + bo;
                else if (region == 1) src = (const char*)(g_predth + (size_t)mc                * 128) + bo;
                else                  src = (const char*)(g_objth  + (size_t)edges[2 * mc + 1] * 128) + bo;
                cp16(ab + (uint32_t)(m * 128 + ((ch ^ (m & 7)) * 16)), src + ch * 16, sz);
            }
            const char* bs = (const char*)(Bsrc + (size_t)kt * KTILE_H);
#pragma unroll
            for (int i = 0; i < LIT; i++) {
                int f = tid + i * NTH;
                cp16(bbuf + (uint32_t)(f * 16), bs + f * 16, 16);
            }
        };
        load_stage(0); CP_COMMIT();
        load_stage(1); CP_COMMIT();
        for (int kt = 0; kt < KT; kt++) {
            CP_WAIT1();
            __syncthreads();
            if (kt + 2 < KT) load_stage(kt + 2);
            CP_COMMIT();
            mma_stage(kt % NSTAGE);
        }
        epilogue(row0);
    } else {
        // ---- persistent bulk path: fixed column block, stride over row panels ----
        if (tid == 0) {
#pragma unroll
            for (int b = 0; b < NSTAGE; b++) {
                MBARRIER_INIT(sm + b * 8, 1);            // full: tx-based
                MBARRIER_INIT(sm + 64 + b * 8, NWARPS);  // empty: one arrive per warp
            }
        }
        __syncthreads();

        int npanels = (M + BM - 1) / BM;
        int stride = gridDim.y;
        int nlocal = (npanels - (int)blockIdx.y + stride - 1) / stride;
        if (nlocal <= 0) return;
        int G = nlocal * KT;

        auto issue_g = [&](int g) {
            int p = g / KT, ktl = g % KT;
            int by = blockIdx.y + p * stride;
            int b = g % NSTAGE;
            uint32_t st = tiles + (uint32_t)b * STAGE_BYTES;
            MBARRIER_EXPECT_TX(sm + b * 8, STAGE_BYTES);
            bulk_g2s(st, Abase + ((size_t)by * KT + ktl) * KTILE_H, KTILE_B, sm + b * 8);
            bulk_g2s(st + KTILE_B, Bsrc + (size_t)ktl * KTILE_H, KTILE_B, sm + b * 8);
        };

        bool lead = (tid == 0);
        if (lead) {
            issue_g(0);
            if (1 < G) issue_g(1);
            if (2 < G) issue_g(2);
        }
        int gnext = NSTAGE;
        int fph0 = 0, fph1 = 0, fph2 = 0;
        int eph0 = 0, eph1 = 0, eph2 = 0;

        for (int p = 0; p < nlocal; p++) {
            int row0 = (blockIdx.y + p * stride) * BM;
            acc_clear();
            for (int kt = 0; kt < KT; kt++) {
                int g = p * KT + kt;
                int b = g % NSTAGE;
                int& fph = (b == 0) ? fph0 : (b == 1) ? fph1 : fph2;
                MBARRIER_WAIT_PARITY(sm + b * 8, fph);
                fph ^= 1;
                mma_stage(b);
                if (lane == 0) MBARRIER_ARRIVE(sm + 64 + b * 8);
                if (lead && gnext < G) {
                    int& eph = (b == 0) ? eph0 : (b == 1) ? eph1 : eph2;
                    MBARRIER_WAIT_PARITY(sm + 64 + b * 8, eph);
                    eph ^= 1;
                    issue_g(gnext++);
                }
            }
            epilogue(row0);
        }
    }
}

// ---------------------------------------------------------------------------
extern "C" void kernel_launch(void* const* d_in, const int* in_sizes, int n_in,
                              void* d_out, int out_size)
{
    const float* obj   = (const float*)d_in[0];
    const float* pred  = (const float*)d_in[1];
    const int*   edges = (const int*)  d_in[2];
    const float* W1 = (const float*)d_in[3];
    const float* b1 = (const float*)d_in[4];
    const float* W2 = (const float*)d_in[5];
    const float* b2 = (const float*)d_in[6];
    const float* W3 = (const float*)d_in[7];
    const float* b3 = (const float*)d_in[8];
    const float* W4 = (const float*)d_in[9];
    const float* b4 = (const float*)d_in[10];

    float* out     = (float*)d_out;
    float* out_obj = out;                           // (NOBJ, 128)
    float* out_p   = out + (size_t)NOBJ * D_OUTK;   // (NT, 128)

    cudaFuncSetAttribute((const void*)hgemm<0, 2>, cudaFuncAttributeMaxDynamicSharedMemorySize, SMEMB);
    cudaFuncSetAttribute((const void*)hgemm<1, 4>, cudaFuncAttributeMaxDynamicSharedMemorySize, SMEMB);
    cudaFuncSetAttribute((const void*)hgemm<2, 4>, cudaFuncAttributeMaxDynamicSharedMemorySize, SMEMB);
    cudaFuncSetAttribute((const void*)hgemm<3, 2>, cudaFuncAttributeMaxDynamicSharedMemorySize, SMEMB);

    zero_counts<<<(NOBJ + 255) / 256, 256>>>();
    prep_kernel<<<NB_TOTAL, 256>>>(obj, pred, edges, W1, W2, W3, W4);

    int gy_t = (NT + BM - 1) / BM;    // 1563

    hgemm<0, 2><<<dim3(4, gy_t), 256, SMEMB>>>(edges, b1, nullptr, NT);
    hgemm<1, 4><<<dim3(9, 33), 128, SMEMB>>>(edges, b2, out_p, NT);     // 297 CTAs
    normalize_h<<<(NOBJ * HID / 4 + 255) / 256, 256>>>();
    hgemm<2, 4><<<dim3(4, 74), 128, SMEMB>>>(edges, b3, nullptr, NOBJ); // 296 CTAs
    hgemm<3, 2><<<dim3(1, 296), 256, SMEMB>>>(edges, b4, out_obj, NOBJ);
}

// round 16
// speedup vs baseline: 1.0628x; 1.0628x over previous
#include <cuda_runtime.h>
#include <cuda_fp16.h>
#include <cstdint>

#define D_IN   128
#define HID    512
#define D_OUTK 128
#define NOBJ   100000
#define NT     200000

#define BM 128
#define BN 128
#define BK 64
#define KTILE_H 8192                     // halfs per 16KB tile (128 rows x 64 halfs)
#define KTILE_B 16384
#define STAGE_BYTES (2 * KTILE_B)        // A + B = 32 KB
#define NSTAGE 3
#define SMEMB (1024 + NSTAGE * STAGE_BYTES)
#define NPANEL_T 1563                    // ceil(NT/128)
#define NPANEL_O 782                     // ceil(NOBJ/128)

// Scratch (device globals — no allocation allowed). Zero-init; tails beyond M
// are never written and stay zero across replays.
__device__ __align__(16) __half g_h[(size_t)NPANEL_T * 8 * KTILE_H];   // packed tiles
__device__ __align__(16) float  g_pooled[(size_t)NOBJ * HID];
__device__ __align__(16) __half g_ph[(size_t)NPANEL_O * 8 * KTILE_H];  // pooledh packed
__device__ __align__(16) __half g_tp[(size_t)NPANEL_O * 8 * KTILE_H];  // tmph packed
__device__ __align__(16) float  g_counts[NOBJ];
__device__ __align__(16) __half g_objth[(size_t)NOBJ * D_IN];
__device__ __align__(16) __half g_predth[(size_t)NT * D_IN];
// Weights packed as [nblock][ktile][16KB swizzled tile]
__device__ __align__(16) __half g_W1P[(size_t)4 * 6 * KTILE_H];
__device__ __align__(16) __half g_W2P[(size_t)9 * 8 * KTILE_H];
__device__ __align__(16) __half g_W3P[(size_t)4 * 8 * KTILE_H];
__device__ __align__(16) __half g_W4P[(size_t)1 * 8 * KTILE_H];

// ---------------------------------------------------------------------------
__device__ __forceinline__ void mma_f16(float* c, const uint32_t* a, const uint32_t* b) {
    asm volatile(
        "mma.sync.aligned.m16n8k16.row.col.f32.f16.f16.f32 "
        "{%0,%1,%2,%3}, {%4,%5,%6,%7}, {%8,%9}, {%0,%1,%2,%3};"
        : "+f"(c[0]), "+f"(c[1]), "+f"(c[2]), "+f"(c[3])
        : "r"(a[0]), "r"(a[1]), "r"(a[2]), "r"(a[3]), "r"(b[0]), "r"(b[1]));
}

__device__ __forceinline__ void ldsm4(uint32_t& r0, uint32_t& r1, uint32_t& r2,
                                      uint32_t& r3, uint32_t addr) {
    asm volatile("ldmatrix.sync.aligned.m8n8.x4.shared.b16 {%0,%1,%2,%3}, [%4];"
                 : "=r"(r0), "=r"(r1), "=r"(r2), "=r"(r3) : "r"(addr));
}

__device__ __forceinline__ void cp16(uint32_t d, const void* s, int sz) {
    asm volatile("cp.async.cg.shared.global [%0], [%1], 16, %2;"
                 :: "r"(d), "l"(s), "r"(sz));
}
#define CP_COMMIT() asm volatile("cp.async.commit_group;" ::: "memory")
#define CP_WAIT1()  asm volatile("cp.async.wait_group 1;" ::: "memory")

__device__ __forceinline__ void bulk_g2s(uint32_t dst, const void* src,
                                         int bytes, uint32_t mbar) {
    asm volatile("cp.async.bulk.shared::cta.global.mbarrier::complete_tx::bytes "
                 "[%0], [%1], %2, [%3];"
                 :: "r"(dst), "l"(src), "r"(bytes), "r"(mbar) : "memory");
}

#define MBARRIER_INIT(mbar, count) \
    asm volatile("mbarrier.init.shared.b64 [%0], %1;" \
                 :: "r"((uint32_t)(mbar)), "r"((uint32_t)(count)) : "memory")
#define MBARRIER_EXPECT_TX(mbar, tx) \
    asm volatile("mbarrier.arrive.expect_tx.shared.b64 _, [%0], %1;" \
                 :: "r"((uint32_t)(mbar)), "r"((uint32_t)(tx)) : "memory")
#define MBARRIER_ARRIVE(mbar) \
    asm volatile("mbarrier.arrive.shared.b64 _, [%0];" \
                 :: "r"((uint32_t)(mbar)) : "memory")
#define MBARRIER_WAIT_PARITY(mbar_smem_addr, phase_parity) do { \
    uint32_t _mbar = (uint32_t)(mbar_smem_addr); \
    uint32_t _parity = (uint32_t)(phase_parity); \
    uint32_t _done; \
    asm volatile("{\n\t.reg .pred p;\n\t" \
        "mbarrier.try_wait.parity.acquire.cta.shared::cta.b64 p, [%1], %2;\n\t" \
        "selp.b32 %0, 1, 0, p;\n\t}" \
        : "=r"(_done) : "r"(_mbar), "r"(_parity) : "memory"); \
    if (!_done) { \
        asm volatile("{\n\t.reg .pred P1;\n\t" \
            "WAIT_LOOP_%=:\n\t" \
            "mbarrier.try_wait.parity.acquire.cta.shared::cta.b64 P1, [%0], %1, 0x989680;\n\t" \
            "@P1 bra.uni WAIT_DONE_%=;\n\t" \
            "bra.uni WAIT_LOOP_%=;\n\t" \
            "WAIT_DONE_%=:\n\t}" \
            :: "r"(_mbar), "r"(_parity) : "memory"); \
    } \
} while(0)

__device__ __forceinline__ void red_add_v4(float* addr, float a, float b,
                                           float c, float d) {
    asm volatile("red.global.add.v4.f32 [%0], {%1, %2, %3, %4};"
                 :: "l"(addr), "f"(a), "f"(b), "f"(c), "f"(d) : "memory");
}

// Packed tile offset (in halfs) for element (row r, col c) of a K=512 matrix.
__device__ __forceinline__ size_t packed_off(int r, int c) {
    int p = r >> 7, m = r & 127, kt = c >> 6, ch = (c & 63) >> 3, rem = c & 7;
    return ((size_t)(p * 8 + kt)) * KTILE_H
         + (size_t)((m * 128 + ((ch ^ (m & 7)) * 16)) >> 1) + rem;
}

// ---------------------------------------------------------------------------
__global__ void zero_counts() {
    int i = blockIdx.x * blockDim.x + threadIdx.x;
    if (i < NOBJ) g_counts[i] = 0.f;
}

#define NB_POOL  50000
#define NB_OBJ   12500
#define NB_PRED  25000
#define NB_W1    768
#define NB_W2    2304
#define NB_W3    1024
#define NB_W4    256
#define NB_CNT   782
#define NB_TOTAL (NB_POOL + NB_OBJ + NB_PRED + NB_W1 + NB_W2 + NB_W3 + NB_W4 + NB_CNT)

__device__ __forceinline__ void cvt_sec(const float* src, __half* dst, int i) {
    float4 v = ((const float4*)src)[i];
    __half2* d2 = (__half2*)dst;
    d2[2 * i]     = __floats2half2_rn(v.x, v.y);
    d2[2 * i + 1] = __floats2half2_rn(v.z, v.w);
}
// Pack W (K x N, row-major) into swizzled tiles WP[nb][kt][16KB]
__device__ __forceinline__ void cvtT_pack(const float* W, __half* WP, int K, int N, int idx) {
    int n = idx / K, k = idx - n * K;
    int nb = n >> 7, nl = n & 127, kt = k >> 6, ch = (k & 63) >> 3, rem = k & 7;
    int KTI = K / 64;
    size_t off = ((size_t)(nb * KTI + kt)) * KTILE_H
               + (size_t)((nl * 128 + ((ch ^ (nl & 7)) * 16)) >> 1) + rem;
    WP[off] = __float2half_rn(W[(size_t)k * N + n]);
}

__global__ void prep_kernel(const float* __restrict__ obj, const float* __restrict__ pred,
                            const int* __restrict__ edges,
                            const float* __restrict__ W1, const float* __restrict__ W2,
                            const float* __restrict__ W3, const float* __restrict__ W4)
{
    int b = blockIdx.x;
    int t = threadIdx.x;
    if (b < NB_POOL) {
        int i = b * 256 + t;
        ((float4*)g_pooled)[i] = make_float4(0.f, 0.f, 0.f, 0.f);
        return;
    }
    b -= NB_POOL;
    if (b < NB_OBJ)  { cvt_sec(obj,  g_objth,  b * 256 + t); return; }
    b -= NB_OBJ;
    if (b < NB_PRED) { cvt_sec(pred, g_predth, b * 256 + t); return; }
    b -= NB_PRED;
    if (b < NB_W1) { cvtT_pack(W1, g_W1P, 384, 512,  b * 256 + t); return; }
    b -= NB_W1;
    if (b < NB_W2) { cvtT_pack(W2, g_W2P, 512, 1152, b * 256 + t); return; }
    b -= NB_W2;
    if (b < NB_W3) { cvtT_pack(W3, g_W3P, 512, 512,  b * 256 + t); return; }
    b -= NB_W3;
    if (b < NB_W4) { cvtT_pack(W4, g_W4P, 512, 128,  b * 256 + t); return; }
    b -= NB_W4;
    {
        int e = b * 256 + t;
        if (e < NT) {
            atomicAdd(&g_counts[edges[2 * e]],     1.f);
            atomicAdd(&g_counts[edges[2 * e + 1]], 1.f);
        }
    }
}

// g_ph[packed(r,c)] = half(pooled[r][c] / max(counts[r],1))
__global__ void normalize_h() {
    int i = blockIdx.x * blockDim.x + threadIdx.x;
    if (i < (NOBJ * HID) / 4) {
        int r = i >> 7;
        int c = (i & 127) * 4;
        float sc = 1.f / fmaxf(g_counts[r], 1.f);
        float4 v = ((const float4*)g_pooled)[i];
        __half* dst = g_ph + packed_off(r, c);
        *(__half2*)(dst)     = __floats2half2_rn(v.x * sc, v.y * sc);
        *(__half2*)(dst + 2) = __floats2half2_rn(v.z * sc, v.w * sc);
    }
}

// ---------------------------------------------------------------------------
// MF = m-fragments per warp (2 -> 32x64 tile, 256 thr; 4 -> 64x64 tile, 128 thr).
// KIND 0: g_h(packed) = h(relu(gather @ W1 + b1))     M=NT,   K=384  [cp.async A + bulk B]
// KIND 1: scatter/out_p from relu(h @ W2 + b2)        M=NT,   K=512  [bulk]
// KIND 2: g_tp(packed) = h(relu(ph @ W3 + b3))        M=NOBJ, K=512  [bulk]
// KIND 3: out_obj = relu(tp @ W4 + b4)                M=NOBJ, K=512  [bulk]
template<int KIND, int MF>
__global__ void __launch_bounds__(512 / MF, 2) hgemm(const int* __restrict__ edges,
                                                     const float* __restrict__ bias,
                                                     float* __restrict__ out, int M)
{
    constexpr int K  = (KIND == 0) ? 384 : 512;
    constexpr int KT = K / BK;
    constexpr int MWARPS = 8 / MF;
    constexpr int NTH = MWARPS * 2 * 32;
    constexpr int NWARPS = NTH / 32;
    constexpr int LIT = 1024 / NTH;

    extern __shared__ __align__(16) char sh[];
    uint32_t sm = (uint32_t)__cvta_generic_to_shared(sh);
    uint32_t tiles = sm + 1024;
    // mbarriers: full[b] at sm + b*8, empty[b] at sm + 64 + b*8

    int tid = threadIdx.x, lane = tid & 31, w = tid >> 5;
    int wm = w % MWARPS, wn = w / MWARPS;
    int gr = lane >> 2, ct = lane & 3;
    int sel = lane >> 3, lr = lane & 7;
    int row0 = blockIdx.y * BM;
    int col0 = blockIdx.x * BN;

    int mode = 0, pcol = 0;
    if (KIND == 1) {
        int bx = blockIdx.x;
        if (bx < 4)       { mode = 0; pcol = bx * 128; }
        else if (bx == 4) { mode = 1; pcol = 0; }
        else              { mode = 2; pcol = (bx - 5) * 128; }
    }

    // Packed sources
    const __half* Bsrc = (KIND == 0) ? g_W1P + (size_t)(blockIdx.x * 6) * KTILE_H
                       : (KIND == 1) ? g_W2P + (size_t)(blockIdx.x * 8) * KTILE_H
                       : (KIND == 2) ? g_W3P + (size_t)(blockIdx.x * 8) * KTILE_H
                                     : g_W4P;
    const __half* Asrc = (KIND == 1) ? g_h  + (size_t)(blockIdx.y * 8) * KTILE_H
                       : (KIND == 2) ? g_ph + (size_t)(blockIdx.y * 8) * KTILE_H
                                     : g_tp + (size_t)(blockIdx.y * 8) * KTILE_H;

    float acc[MF][8][4];
#pragma unroll
    for (int i = 0; i < MF; i++)
#pragma unroll
        for (int j = 0; j < 8; j++)
#pragma unroll
            for (int k = 0; k < 4; k++) acc[i][j][k] = 0.f;

    int a_row[MF];
#pragma unroll
    for (int mf = 0; mf < MF; mf++)
        a_row[mf] = wm * (16 * MF) + mf * 16 + lr + ((sel & 1) << 3);
    int b_row[4];
#pragma unroll
    for (int p = 0; p < 4; p++)
        b_row[p] = wn * 64 + p * 16 + lr + ((sel >> 1) << 3);

    auto mma_stage = [&](int b) {
        uint32_t abase = tiles + (uint32_t)b * STAGE_BYTES;
        uint32_t bbase = abase + KTILE_B;
#pragma unroll
        for (int kb = 0; kb < BK / 16; kb++) {
            uint32_t a[MF][4], bf[8][2];
            int a_ch = 2 * kb + (sel >> 1);
#pragma unroll
            for (int mf = 0; mf < MF; mf++) {
                int r = a_row[mf];
                ldsm4(a[mf][0], a[mf][1], a[mf][2], a[mf][3],
                      abase + (uint32_t)(r * 128 + ((a_ch ^ (r & 7)) * 16)));
            }
            int b_ch = 2 * kb + (sel & 1);
#pragma unroll
            for (int p = 0; p < 4; p++) {
                int r = b_row[p];
                ldsm4(bf[2 * p][0], bf[2 * p][1], bf[2 * p + 1][0], bf[2 * p + 1][1],
                      bbase + (uint32_t)(r * 128 + ((b_ch ^ (r & 7)) * 16)));
            }
#pragma unroll
            for (int mf = 0; mf < MF; mf++)
#pragma unroll
                for (int nf = 0; nf < 8; nf++)
                    mma_f16(acc[mf][nf], a[mf], bf[nf]);
        }
    };

    if (KIND == 0) {
        // ---- A: cp.async gather; B: lead-thread bulk copy (contiguous tile) ----
        if (tid == 0) {
#pragma unroll
            for (int b = 0; b < NSTAGE; b++) MBARRIER_INIT(sm + b * 8, 1);
        }
        __syncthreads();
        auto loadA = [&](int kt) {
            int k0 = kt * BK;
            uint32_t ab = tiles + (uint32_t)(kt % NSTAGE) * STAGE_BYTES;
#pragma unroll
            for (int i = 0; i < LIT; i++) {
                int f = tid + i * NTH;
                int m = f >> 3, ch = f & 7;
                int mg = row0 + m;
                int sz = (mg < M) ? 16 : 0;
                int mc = (mg < M) ? mg : M - 1;
                int region = k0 >> 7;
                int bo = (k0 & 127) * 2;
                const char* src;
                if (region == 0)      src = (const char*)(g_objth  + (size_t)edges[2 * mc]     * 128) + bo;
                else if (region == 1) src = (const char*)(g_predth + (size_t)mc                * 128) + bo;
                else                  src = (const char*)(g_objth  + (size_t)edges[2 * mc + 1] * 128) + bo;
                cp16(ab + (uint32_t)(m * 128 + ((ch ^ (m & 7)) * 16)), src + ch * 16, sz);
            }
        };
        auto issueB = [&](int kt) {
            int b = kt % NSTAGE;
            MBARRIER_EXPECT_TX(sm + b * 8, KTILE_B);
            bulk_g2s(tiles + (uint32_t)b * STAGE_BYTES + KTILE_B,
                     Bsrc + (size_t)kt * KTILE_H, KTILE_B, sm + b * 8);
        };
        bool lead = (tid == 0);
        loadA(0); CP_COMMIT();
        loadA(1); CP_COMMIT();
        if (lead) { issueB(0); issueB(1); }
        int fph0 = 0, fph1 = 0, fph2 = 0;
        for (int kt = 0; kt < KT; kt++) {
            CP_WAIT1();
            __syncthreads();
            if (kt + 2 < KT) {
                loadA(kt + 2);
                if (lead) issueB(kt + 2);
            }
            CP_COMMIT();
            int b = kt % NSTAGE;
            int& fph = (b == 0) ? fph0 : (b == 1) ? fph1 : fph2;
            MBARRIER_WAIT_PARITY(sm + b * 8, fph);
            fph ^= 1;
            mma_stage(b);
        }
    } else {
        // ---- bulk path, sync-free producer/consumer mbarrier ring ----
        if (tid == 0) {
#pragma unroll
            for (int b = 0; b < NSTAGE; b++) {
                MBARRIER_INIT(sm + b * 8, 1);            // full: tx-based
                MBARRIER_INIT(sm + 64 + b * 8, NWARPS);  // empty: one arrive per warp
            }
        }
        __syncthreads();
        auto issue = [&](int kt) {
            int b = kt % NSTAGE;
            uint32_t st = tiles + (uint32_t)b * STAGE_BYTES;
            MBARRIER_EXPECT_TX(sm + b * 8, STAGE_BYTES);
            bulk_g2s(st, Asrc + (size_t)kt * KTILE_H, KTILE_B, sm + b * 8);
            bulk_g2s(st + KTILE_B, Bsrc + (size_t)kt * KTILE_H, KTILE_B, sm + b * 8);
        };
        bool lead = (tid == 0);
        if (lead) { issue(0); issue(1); if (2 < KT) issue(2); }
        int fph0 = 0, fph1 = 0, fph2 = 0;
        int eph0 = 0, eph1 = 0, eph2 = 0;
        for (int kt = 0; kt < KT; kt++) {
            int b = kt % NSTAGE;
            int& fph = (b == 0) ? fph0 : (b == 1) ? fph1 : fph2;
            MBARRIER_WAIT_PARITY(sm + b * 8, fph);
            fph ^= 1;
            mma_stage(b);
            if (lane == 0) MBARRIER_ARRIVE(sm + 64 + b * 8);
            if (lead && kt + NSTAGE < KT) {
                int& eph = (b == 0) ? eph0 : (b == 1) ? eph1 : eph2;
                MBARRIER_WAIT_PARITY(sm + 64 + b * 8, eph);
                eph ^= 1;
                issue(kt + NSTAGE);
            }
        }
    }

    // ---- epilogue ----
    float bb[8][2];
#pragma unroll
    for (int nf = 0; nf < 8; nf++) {
        int c = col0 + wn * 64 + nf * 8 + ct * 2;
        bb[nf][0] = bias[c]; bb[nf][1] = bias[c + 1];
    }

    if (KIND == 1 && mode != 1) {
        int halfsel = ct & 1;
        int q = ct >> 1;
#pragma unroll
        for (int mf = 0; mf < MF; mf++) {
            int rbase = row0 + wm * (16 * MF) + mf * 16 + gr;
            int myrow = rbase + (halfsel ? 8 : 0);
            bool valid = myrow < M;
            int sidx = 0;
            if (valid) sidx = (mode == 0) ? edges[2 * myrow] : edges[2 * myrow + 1];
            float* dstrow = g_pooled + (size_t)sidx * HID + pcol + wn * 64 + q * 4;
#pragma unroll
            for (int nf = 0; nf < 8; nf++) {
                float v0 = fmaxf(acc[mf][nf][0] + bb[nf][0], 0.f);
                float v1 = fmaxf(acc[mf][nf][1] + bb[nf][1], 0.f);
                float v2 = fmaxf(acc[mf][nf][2] + bb[nf][0], 0.f);
                float v3 = fmaxf(acc[mf][nf][3] + bb[nf][1], 0.f);
                float s0 = halfsel ? v0 : v2;
                float s1 = halfsel ? v1 : v3;
                float p0 = __shfl_xor_sync(0xffffffffu, s0, 1);
                float p1 = __shfl_xor_sync(0xffffffffu, s1, 1);
                float o0 = halfsel ? p0 : v0;
                float o1 = halfsel ? p1 : v1;
                float o2 = halfsel ? v2 : p0;
                float o3 = halfsel ? v3 : p1;
                if (valid) red_add_v4(dstrow + nf * 8, o0, o1, o2, o3);
            }
        }
    } else {
#pragma unroll
        for (int mf = 0; mf < MF; mf++)
#pragma unroll
            for (int half = 0; half < 2; half++) {
                int r = row0 + wm * (16 * MF) + mf * 16 + gr + half * 8;
                if (r >= M) continue;
                if (KIND == 0 || KIND == 2) {
                    __half* base = (KIND == 0) ? g_h : g_tp;
#pragma unroll
                    for (int nf = 0; nf < 8; nf++) {
                        int c = col0 + wn * 64 + nf * 8 + ct * 2;
                        float x = fmaxf(acc[mf][nf][half * 2 + 0] + bb[nf][0], 0.f);
                        float y = fmaxf(acc[mf][nf][half * 2 + 1] + bb[nf][1], 0.f);
                        *(__half2*)(base + packed_off(r, c)) = __floats2half2_rn(x, y);
                    }
                } else {  // KIND 3 or KIND 1 mode==1
                    int cbase = wn * 64 + ct * 2;
                    float* dst = out + (size_t)r * D_OUTK + cbase;
#pragma unroll
                    for (int nf = 0; nf < 8; nf++) {
                        float2 o;
                        o.x = fmaxf(acc[mf][nf][half * 2 + 0] + bb[nf][0], 0.f);
                        o.y = fmaxf(acc[mf][nf][half * 2 + 1] + bb[nf][1], 0.f);
                        *(float2*)(dst + nf * 8) = o;
                    }
                }
            }
    }
}

// ---------------------------------------------------------------------------
extern "C" void kernel_launch(void* const* d_in, const int* in_sizes, int n_in,
                              void* d_out, int out_size)
{
    const float* obj   = (const float*)d_in[0];
    const float* pred  = (const float*)d_in[1];
    const int*   edges = (const int*)  d_in[2];
    const float* W1 = (const float*)d_in[3];
    const float* b1 = (const float*)d_in[4];
    const float* W2 = (const float*)d_in[5];
    const float* b2 = (const float*)d_in[6];
    const float* W3 = (const float*)d_in[7];
    const float* b3 = (const float*)d_in[8];
    const float* W4 = (const float*)d_in[9];
    const float* b4 = (const float*)d_in[10];

    float* out     = (float*)d_out;
    float* out_obj = out;                           // (NOBJ, 128)
    float* out_p   = out + (size_t)NOBJ * D_OUTK;   // (NT, 128)

    cudaFuncSetAttribute((const void*)hgemm<0, 2>, cudaFuncAttributeMaxDynamicSharedMemorySize, SMEMB);
    cudaFuncSetAttribute((const void*)hgemm<1, 4>, cudaFuncAttributeMaxDynamicSharedMemorySize, SMEMB);
    cudaFuncSetAttribute((const void*)hgemm<2, 4>, cudaFuncAttributeMaxDynamicSharedMemorySize, SMEMB);
    cudaFuncSetAttribute((const void*)hgemm<3, 4>, cudaFuncAttributeMaxDynamicSharedMemorySize, SMEMB);

    zero_counts<<<(NOBJ + 255) / 256, 256>>>();
    prep_kernel<<<NB_TOTAL, 256>>>(obj, pred, edges, W1, W2, W3, W4);

    int gy_t = (NT + BM - 1) / BM;    // 1563
    int gy_o = (NOBJ + BM - 1) / BM;  // 782

    hgemm<0, 2><<<dim3(4, gy_t), 256, SMEMB>>>(edges, b1, nullptr, NT);
    hgemm<1, 4><<<dim3(9, gy_t), 128, SMEMB>>>(edges, b2, out_p, NT);
    normalize_h<<<(NOBJ * HID / 4 + 255) / 256, 256>>>();
    hgemm<2, 4><<<dim3(4, gy_o), 128, SMEMB>>>(edges, b3, nullptr, NOBJ);
    hgemm<3, 4><<<dim3(1, gy_o), 128, SMEMB>>>(edges, b4, out_obj, NOBJ);
}